// round 16
// baseline (speedup 1.0000x reference)
#include <cuda_runtime.h>

// SE_loss_w_threshold: h,v (8,16384,128) fp32, N scalar.
// out (10 fp32): [mean_Rp, R_per_user[0..7], sum(R_per_user)]
// R16: hybrid load paths. v staged via TMA (4.2KB tiles, depth-2, per-warp
// mbarriers); h read DIRECT from global via LDG.128 (8x16B dedup/instr, no
// overtraffic). Tile halves -> 16 warps/SM (4 blk x 4 warps) + LDG MLP adds
// DRAM demand beyond tile count. Tests the demand-starvation theory cleanly.

#define NUSER 8
#define BATCH 16384
#define ROWF  132                      // v smem row stride (floats), conflict-free
#define VTILE (NUSER * ROWF)           // 1056 floats = 4224 B
#define WPB   4
#define THREADS (WPB * 32)
#define GRID  592                      // 148 SMs * 4 blocks/SM, single wave
#define NW    (GRID * WPB)             // 2368 warps
#define SMEM_BYTES (2 * WPB * VTILE * 4)   // 33792 B
#define TX_BYTES (NUSER * 512)         // 4096 B per staged v tile
#define USTRIDE ((size_t)BATCH * 128)  // floats between user planes

typedef unsigned long long u64;

__device__ double gAcc[9];
__device__ unsigned int gCount = 0;

__device__ __forceinline__ u64 ffma2(u64 a, u64 b, u64 c) {
    u64 d;
    asm("fma.rn.f32x2 %0, %1, %2, %3;" : "=l"(d) : "l"(a), "l"(b), "l"(c));
    return d;
}
__device__ __forceinline__ float hsum2(u64 a) {
    float2 f;
    asm("mov.b64 {%0, %1}, %2;" : "=f"(f.x), "=f"(f.y) : "l"(a));
    return f.x + f.y;
}

#define DOT(re, ip, in, hl, hh, vl, vh)            \
    re = ffma2((hl).x, (vl).x, re);                \
    re = ffma2((hl).y, (vl).y, re);                \
    re = ffma2((hh).x, (vh).x, re);                \
    re = ffma2((hh).y, (vh).y, re);                \
    ip = ffma2((hh).x, (vl).x, ip);                \
    ip = ffma2((hh).y, (vl).y, ip);                \
    in = ffma2((hl).x, (vh).x, in);                \
    in = ffma2((hl).y, (vh).y, in);

struct Acc {
    u64 nrm2;
    u64 re00, ip00, in00;
    u64 re01, ip01, in01;
    u64 re10, ip10, in10;
    u64 re11, ip11, in11;
};

// leader stages one batch's v tile via 8 x 512B bulk copies -> mbar
__device__ __forceinline__ void stageV(const float* __restrict__ vg,
                                       int b, unsigned bufa, unsigned mbar)
{
    asm volatile("mbarrier.arrive.expect_tx.shared.b64 _, [%0], %1;"
                 :: "r"(mbar), "r"(TX_BYTES) : "memory");
    #pragma unroll
    for (int u = 0; u < NUSER; u++) {
        const float* src = vg + (size_t)u * USTRIDE + ((size_t)b << 7);
        asm volatile(
            "cp.async.bulk.shared::cta.global.mbarrier::complete_tx::bytes "
            "[%0], [%1], 512, [%2];"
            :: "r"(bufa + (unsigned)(u * ROWF * 4)), "l"(src), "r"(mbar) : "memory");
    }
}

__device__ __forceinline__ void waitBar(unsigned mbar, int phase) {
    asm volatile(
        "{\n\t"
        ".reg .pred P;\n\t"
        "WL_%=:\n\t"
        "mbarrier.try_wait.parity.acquire.cta.shared::cta.b64 P, [%0], %1, 0x989680;\n\t"
        "@!P bra WL_%=;\n\t"
        "}"
        :: "r"(mbar), "r"(phase) : "memory");
}

// dots: v from smem, h DIRECT via LDG.128 (hb = hg + b*128)
__device__ __forceinline__ void dots(Acc& A, const float* __restrict__ vb,
                                     const float* __restrict__ hb,
                                     int a, int c, int k2, int lane)
{
    const ulonglong2* h0 = (const ulonglong2*)(hb + (size_t)(2 * a)     * USTRIDE);
    const ulonglong2* h1 = (const ulonglong2*)(hb + (size_t)(2 * a + 1) * USTRIDE);
    const float* vc0 = vb + (2 * c) * ROWF;
    const float* vc1 = vc0 + ROWF;
    const int t0 = k2 * 4;

    A.nrm2 = 0ULL;
    A.re00 = A.ip00 = A.in00 = 0ULL;
    A.re01 = A.ip01 = A.in01 = 0ULL;
    A.re10 = A.ip10 = A.in10 = 0ULL;
    A.re11 = A.ip11 = A.in11 = 0ULL;

    #pragma unroll
    for (int u = 0; u < NUSER; u++) {
        const ulonglong2 vv = *(const ulonglong2*)(vb + u * ROWF + (lane << 2));
        A.nrm2 = ffma2(vv.x, vv.x, A.nrm2);
        A.nrm2 = ffma2(vv.y, vv.y, A.nrm2);
    }
    #pragma unroll
    for (int m = 0; m < 8; m++) {
        const int hi = k2 + 2 * m;             // 16B index within 512B row
        const ulonglong2 h0l = __ldg(h0 + hi);
        const ulonglong2 h0h = __ldg(h0 + hi + 16);
        const ulonglong2 h1l = __ldg(h1 + hi);
        const ulonglong2 h1h = __ldg(h1 + hi + 16);
        const int off = t0 + m * 8;
        const ulonglong2 v0l = *(const ulonglong2*)(vc0 + off);
        const ulonglong2 v0h = *(const ulonglong2*)(vc0 + off + 64);
        const ulonglong2 v1l = *(const ulonglong2*)(vc1 + off);
        const ulonglong2 v1h = *(const ulonglong2*)(vc1 + off + 64);

        DOT(A.re00, A.ip00, A.in00, h0l, h0h, v0l, v0h)
        DOT(A.re01, A.ip01, A.in01, h0l, h0h, v1l, v1h)
        DOT(A.re10, A.ip10, A.in10, h1l, h1h, v0l, v0h)
        DOT(A.re11, A.ip11, A.in11, h1l, h1h, v1l, v1h)
    }
}

__device__ __forceinline__ void reduceTail(const Acc& A, float Nval,
                                           int a, int c, int k2,
                                           float& accRp, float& accR0, float& accR1)
{
    float nrm = hsum2(A.nrm2);
    #pragma unroll
    for (int o = 16; o; o >>= 1)
        nrm += __shfl_xor_sync(0xffffffffu, nrm, o);

    float Ar00 = hsum2(A.re00), Ai00 = hsum2(A.ip00) - hsum2(A.in00);
    float Ar01 = hsum2(A.re01), Ai01 = hsum2(A.ip01) - hsum2(A.in01);
    float Ar10 = hsum2(A.re10), Ai10 = hsum2(A.ip10) - hsum2(A.in10);
    float Ar11 = hsum2(A.re11), Ai11 = hsum2(A.ip11) - hsum2(A.in11);

    Ar00 += __shfl_xor_sync(0xffffffffu, Ar00, 16);
    Ai00 += __shfl_xor_sync(0xffffffffu, Ai00, 16);
    Ar01 += __shfl_xor_sync(0xffffffffu, Ar01, 16);
    Ai01 += __shfl_xor_sync(0xffffffffu, Ai01, 16);
    Ar10 += __shfl_xor_sync(0xffffffffu, Ar10, 16);
    Ai10 += __shfl_xor_sync(0xffffffffu, Ai10, 16);
    Ar11 += __shfl_xor_sync(0xffffffffu, Ar11, 16);
    Ai11 += __shfl_xor_sync(0xffffffffu, Ai11, 16);

    const float p00 = fmaf(Ar00, Ar00, Ai00 * Ai00);
    const float p01 = fmaf(Ar01, Ar01, Ai01 * Ai01);
    const float p10 = fmaf(Ar10, Ar10, Ai10 * Ai10);
    const float p11 = fmaf(Ar11, Ar11, Ai11 * Ai11);

    const float d0 = p00, d1 = p11;     // valid on lanes c==a

    float s0 = p00 + p01;
    float s1 = p10 + p11;
    s0 += __shfl_xor_sync(0xffffffffu, s0, 1);
    s1 += __shfl_xor_sync(0xffffffffu, s1, 1);
    s0 += __shfl_xor_sync(0xffffffffu, s0, 2);
    s1 += __shfl_xor_sync(0xffffffffu, s1, 2);

    if (c == a && k2 == 0) {
        const float scale2 = 8.0f / nrm;
        const float sinr0 = __fdividef(d0 * scale2, s0 - d0 + Nval);
        const float sinr1 = __fdividef(d1 * scale2, s1 - d1 + Nval);
        const float R0 = __log2f(1.0f + sinr0);
        const float R1 = __log2f(1.0f + sinr1);
        accR0 += R0;
        accR1 += R1;
        accRp += __exp10f(0.3f - R0) - R0
               + __exp10f(0.3f - R1) - R1;
    }
}

__global__ __launch_bounds__(THREADS, 4)
void se_fused_kernel(const float* __restrict__ hg,
                     const float* __restrict__ vg,
                     const float* __restrict__ Np,
                     float* __restrict__ out, int out_size)
{
    __shared__ __align__(16) float sv[2 * WPB * VTILE];
    __shared__ __align__(8) u64 mbars[WPB][2];
    __shared__ double sAcc[9];
    __shared__ int sLast;

    const int tid  = threadIdx.x;
    const int lane = tid & 31;
    const int wid  = tid >> 5;
    const bool leader = (lane == 0);

    if (tid < 9) sAcc[tid] = 0.0;

    const unsigned mb0 = (unsigned)__cvta_generic_to_shared(&mbars[wid][0]);
    const unsigned mb1 = (unsigned)__cvta_generic_to_shared(&mbars[wid][1]);
    if (leader) {
        asm volatile("mbarrier.init.shared.b64 [%0], 1;" :: "r"(mb0) : "memory");
        asm volatile("mbarrier.init.shared.b64 [%0], 1;" :: "r"(mb1) : "memory");
    }
    asm volatile("fence.proxy.async.shared::cta;" ::: "memory");
    __syncthreads();

    const int gw = blockIdx.x * WPB + wid;

    float* vbuf0 = sv + wid * VTILE;
    float* vbuf1 = sv + (WPB + wid) * VTILE;
    const unsigned vbuf0a = (unsigned)__cvta_generic_to_shared(vbuf0);
    const unsigned vbuf1a = (unsigned)__cvta_generic_to_shared(vbuf1);

    const float Nval = __ldg(Np);

    const int c  = lane & 3;
    const int a  = (lane >> 2) & 3;
    const int k2 = lane >> 4;

    float accRp = 0.0f, accR0 = 0.0f, accR1 = 0.0f;
    Acc A;
    int ph[2] = {0, 0};

    // ---- prologue: two v tiles in flight (gw + NW, gw + 2*NW < BATCH always) ----
    if (leader) {
        stageV(vg, gw, vbuf0a, mb0);
        stageV(vg, gw + NW, vbuf1a, mb1);
    }

    int buf = 0;
    for (int b = gw; b < BATCH; b += NW, buf ^= 1) {
        const unsigned mb = buf ? mb1 : mb0;
        waitBar(mb, ph[buf]); ph[buf] ^= 1;

        dots(A, buf ? vbuf1 : vbuf0, hg + ((size_t)b << 7), a, c, k2, lane);

        __syncwarp();                       // v buffer fully consumed
        const int bp = b + 2 * NW;
        if (leader && bp < BATCH)
            stageV(vg, bp, buf ? vbuf1a : vbuf0a, mb);

        reduceTail(A, Nval, a, c, k2, accRp, accR0, accR1);
    }

    // ---- block-level reduction ----
    if (c == a && k2 == 0) {
        atomicAdd(&sAcc[0],         (double)accRp);
        atomicAdd(&sAcc[1 + 2 * a], (double)accR0);
        atomicAdd(&sAcc[2 + 2 * a], (double)accR1);
    }
    __syncthreads();

    if (tid < 9) atomicAdd(&gAcc[tid], sAcc[tid]);
    __threadfence();
    __syncthreads();

    if (tid == 0) {
        const unsigned old = atomicInc(&gCount, GRID - 1);
        sLast = (old == GRID - 1) ? 1 : 0;
    }
    __syncthreads();

    if (sLast && tid == 0) {
        __threadfence();
        const double inv = 1.0 / (double)BATCH;
        double r[9];
        #pragma unroll
        for (int i = 0; i < 9; i++) {
            r[i] = __ldcg(&gAcc[i]);
            __stcg(&gAcc[i], 0.0);
        }
        double s = 0.0;
        #pragma unroll
        for (int i = 1; i < 9; i++) s += r[i] * inv;
        if (out_size >= 1) out[0] = (float)(r[0] * inv);
        if (out_size >= 10) {
            #pragma unroll
            for (int i = 0; i < 8; i++) out[1 + i] = (float)(r[1 + i] * inv);
            out[9] = (float)s;
        }
    }
}

extern "C" void kernel_launch(void* const* d_in, const int* in_sizes, int n_in,
                              void* d_out, int out_size)
{
    const float* h = (const float*)d_in[0];
    const float* v = (const float*)d_in[1];
    const float* N = (const float*)d_in[2];
    float* out = (float*)d_out;

    se_fused_kernel<<<GRID, THREADS>>>(h, v, N, out, out_size);
}

// round 17
// speedup vs baseline: 1.1931x; 1.1931x over previous
#include <cuda_runtime.h>

// SE_loss_w_threshold: h,v (8,16384,128) fp32, N scalar.
// out (10 fp32): [mean_Rp, R_per_user[0..7], sum(R_per_user)]
// R17: warp-PRIVATE batch pairs. Each warp processes batches (2p,2p+1) from
// one 16.6KB tile staged as 16 x 1KB CONTIGUOUS bulk copies (2x DRAM row
// locality vs 512B, half the request count). No cross-warp coupling.
// 2 warps/block, 3 blocks/SM, depth-2 pipeline, R9-style in-pair overlap.

#define NUSER 8
#define BATCH 16384
#define NPAIR 8192
#define PROW  260                      // floats per user row (256 data + 4 pad)
#define VOFF  (NUSER * PROW)           // v tile offset (floats)
#define PBUF  (2 * NUSER * PROW)       // h+v pair tile: 4160 floats = 16640 B
#define WPB   2
#define THREADS (WPB * 32)
#define GRID  444                      // 148 SMs * 3 blocks/SM
#define NP    (GRID * WPB)             // 888 warps = pair-streams
#define SMEM_BYTES (2 * WPB * PBUF * 4)    // 66560 B
#define TX_BYTES (2 * NUSER * 1024)    // 16384 B per pair tile
#define USTRIDE ((size_t)BATCH * 128)  // floats between user planes

typedef unsigned long long u64;

__device__ double gAcc[9];
__device__ unsigned int gCount = 0;

__device__ __forceinline__ u64 ffma2(u64 a, u64 b, u64 c) {
    u64 d;
    asm("fma.rn.f32x2 %0, %1, %2, %3;" : "=l"(d) : "l"(a), "l"(b), "l"(c));
    return d;
}
__device__ __forceinline__ float hsum2(u64 a) {
    float2 f;
    asm("mov.b64 {%0, %1}, %2;" : "=f"(f.x), "=f"(f.y) : "l"(a));
    return f.x + f.y;
}

#define DOT(re, ip, in, hl, hh, vl, vh)            \
    re = ffma2((hl).x, (vl).x, re);                \
    re = ffma2((hl).y, (vl).y, re);                \
    re = ffma2((hh).x, (vh).x, re);                \
    re = ffma2((hh).y, (vh).y, re);                \
    ip = ffma2((hh).x, (vl).x, ip);                \
    ip = ffma2((hh).y, (vl).y, ip);                \
    in = ffma2((hl).x, (vh).x, in);                \
    in = ffma2((hl).y, (vh).y, in);

struct Acc {
    u64 nrm2;
    u64 re00, ip00, in00;
    u64 re01, ip01, in01;
    u64 re10, ip10, in10;
    u64 re11, ip11, in11;
};

// lane 0: stage pair-tile for pair pi (batches 2pi,2pi+1): 16 x 1KB contiguous
__device__ __forceinline__ void stagePair(const float* __restrict__ hg,
                                          const float* __restrict__ vg,
                                          int pi, unsigned bufa, unsigned mbar)
{
    const size_t b0f = (size_t)(pi << 1) << 7;     // float offset of batch 2pi
    asm volatile("mbarrier.arrive.expect_tx.shared.b64 _, [%0], %1;"
                 :: "r"(mbar), "r"(TX_BYTES) : "memory");
    #pragma unroll
    for (int u = 0; u < NUSER; u++) {
        const size_t g = (size_t)u * USTRIDE + b0f;
        const unsigned hdst = bufa + (unsigned)(u * PROW * 4);
        asm volatile(
            "cp.async.bulk.shared::cta.global.mbarrier::complete_tx::bytes "
            "[%0], [%1], 1024, [%2];"
            :: "r"(hdst), "l"(hg + g), "r"(mbar) : "memory");
        asm volatile(
            "cp.async.bulk.shared::cta.global.mbarrier::complete_tx::bytes "
            "[%0], [%1], 1024, [%2];"
            :: "r"(hdst + (unsigned)(VOFF * 4)), "l"(vg + g), "r"(mbar) : "memory");
    }
}

__device__ __forceinline__ void waitBar(unsigned mbar, int phase) {
    asm volatile(
        "{\n\t"
        ".reg .pred P;\n\t"
        "WL_%=:\n\t"
        "mbarrier.try_wait.parity.acquire.cta.shared::cta.b64 P, [%0], %1, 0x989680;\n\t"
        "@!P bra WL_%=;\n\t"
        "}"
        :: "r"(mbar), "r"(phase) : "memory");
}

// LDS + FFMA for one batch; wbs = pair buffer + sub*128 floats
__device__ __forceinline__ void dots(Acc& A, const float* __restrict__ wbs,
                                     int a, int c, int t0, int lane)
{
    const float* hr0 = wbs + (2 * a) * PROW;
    const float* hr1 = hr0 + PROW;
    const float* vc0 = wbs + VOFF + (2 * c) * PROW;
    const float* vc1 = vc0 + PROW;

    A.nrm2 = 0ULL;
    A.re00 = A.ip00 = A.in00 = 0ULL;
    A.re01 = A.ip01 = A.in01 = 0ULL;
    A.re10 = A.ip10 = A.in10 = 0ULL;
    A.re11 = A.ip11 = A.in11 = 0ULL;

    #pragma unroll
    for (int u = 0; u < NUSER; u++) {
        const ulonglong2 vv = *(const ulonglong2*)(wbs + VOFF + u * PROW + (lane << 2));
        A.nrm2 = ffma2(vv.x, vv.x, A.nrm2);
        A.nrm2 = ffma2(vv.y, vv.y, A.nrm2);
    }
    #pragma unroll
    for (int m = 0; m < 8; m++) {
        const int off = t0 + m * 8;
        const ulonglong2 h0l = *(const ulonglong2*)(hr0 + off);
        const ulonglong2 h0h = *(const ulonglong2*)(hr0 + off + 64);
        const ulonglong2 h1l = *(const ulonglong2*)(hr1 + off);
        const ulonglong2 h1h = *(const ulonglong2*)(hr1 + off + 64);
        const ulonglong2 v0l = *(const ulonglong2*)(vc0 + off);
        const ulonglong2 v0h = *(const ulonglong2*)(vc0 + off + 64);
        const ulonglong2 v1l = *(const ulonglong2*)(vc1 + off);
        const ulonglong2 v1h = *(const ulonglong2*)(vc1 + off + 64);

        DOT(A.re00, A.ip00, A.in00, h0l, h0h, v0l, v0h)
        DOT(A.re01, A.ip01, A.in01, h0l, h0h, v1l, v1h)
        DOT(A.re10, A.ip10, A.in10, h1l, h1h, v0l, v0h)
        DOT(A.re11, A.ip11, A.in11, h1l, h1h, v1l, v1h)
    }
}

__device__ __forceinline__ void reduceTail(const Acc& A, float Nval,
                                           int a, int c, int k2,
                                           float& accRp, float& accR0, float& accR1)
{
    float nrm = hsum2(A.nrm2);
    #pragma unroll
    for (int o = 16; o; o >>= 1)
        nrm += __shfl_xor_sync(0xffffffffu, nrm, o);

    float Ar00 = hsum2(A.re00), Ai00 = hsum2(A.ip00) - hsum2(A.in00);
    float Ar01 = hsum2(A.re01), Ai01 = hsum2(A.ip01) - hsum2(A.in01);
    float Ar10 = hsum2(A.re10), Ai10 = hsum2(A.ip10) - hsum2(A.in10);
    float Ar11 = hsum2(A.re11), Ai11 = hsum2(A.ip11) - hsum2(A.in11);

    Ar00 += __shfl_xor_sync(0xffffffffu, Ar00, 16);
    Ai00 += __shfl_xor_sync(0xffffffffu, Ai00, 16);
    Ar01 += __shfl_xor_sync(0xffffffffu, Ar01, 16);
    Ai01 += __shfl_xor_sync(0xffffffffu, Ai01, 16);
    Ar10 += __shfl_xor_sync(0xffffffffu, Ar10, 16);
    Ai10 += __shfl_xor_sync(0xffffffffu, Ai10, 16);
    Ar11 += __shfl_xor_sync(0xffffffffu, Ar11, 16);
    Ai11 += __shfl_xor_sync(0xffffffffu, Ai11, 16);

    const float p00 = fmaf(Ar00, Ar00, Ai00 * Ai00);
    const float p01 = fmaf(Ar01, Ar01, Ai01 * Ai01);
    const float p10 = fmaf(Ar10, Ar10, Ai10 * Ai10);
    const float p11 = fmaf(Ar11, Ar11, Ai11 * Ai11);

    const float d0 = p00, d1 = p11;     // valid on lanes c==a

    float s0 = p00 + p01;
    float s1 = p10 + p11;
    s0 += __shfl_xor_sync(0xffffffffu, s0, 1);
    s1 += __shfl_xor_sync(0xffffffffu, s1, 1);
    s0 += __shfl_xor_sync(0xffffffffu, s0, 2);
    s1 += __shfl_xor_sync(0xffffffffu, s1, 2);

    if (c == a && k2 == 0) {
        const float scale2 = 8.0f / nrm;
        const float sinr0 = __fdividef(d0 * scale2, s0 - d0 + Nval);
        const float sinr1 = __fdividef(d1 * scale2, s1 - d1 + Nval);
        const float R0 = __log2f(1.0f + sinr0);
        const float R1 = __log2f(1.0f + sinr1);
        accR0 += R0;
        accR1 += R1;
        accRp += __exp10f(0.3f - R0) - R0
               + __exp10f(0.3f - R1) - R1;
    }
}

__global__ __launch_bounds__(THREADS, 3)
void se_fused_kernel(const float* __restrict__ hg,
                     const float* __restrict__ vg,
                     const float* __restrict__ Np,
                     float* __restrict__ out, int out_size)
{
    extern __shared__ __align__(16) float sh[];
    __shared__ __align__(8) u64 mbars[WPB][2];
    __shared__ double sAcc[9];
    __shared__ int sLast;

    const int tid  = threadIdx.x;
    const int lane = tid & 31;
    const int wid  = tid >> 5;
    const bool leader = (lane == 0);

    if (tid < 9) sAcc[tid] = 0.0;

    const unsigned mb0 = (unsigned)__cvta_generic_to_shared(&mbars[wid][0]);
    const unsigned mb1 = (unsigned)__cvta_generic_to_shared(&mbars[wid][1]);
    if (leader) {
        asm volatile("mbarrier.init.shared.b64 [%0], 1;" :: "r"(mb0) : "memory");
        asm volatile("mbarrier.init.shared.b64 [%0], 1;" :: "r"(mb1) : "memory");
    }
    asm volatile("fence.proxy.async.shared::cta;" ::: "memory");
    __syncthreads();

    float* buf0f = sh + (wid * 2) * PBUF;
    float* buf1f = buf0f + PBUF;
    const unsigned buf0a = (unsigned)__cvta_generic_to_shared(buf0f);
    const unsigned buf1a = (unsigned)__cvta_generic_to_shared(buf1f);

    const float Nval = __ldg(Np);

    const int c  = lane & 3;
    const int a  = (lane >> 2) & 3;
    const int k2 = lane >> 4;
    const int t0 = k2 * 4;

    const int P = blockIdx.x * WPB + wid;      // pair stream id

    float accRp = 0.0f, accR0 = 0.0f, accR1 = 0.0f;
    Acc A, B;
    int ph0 = 0, ph1 = 0;

    // ---- prologue: two pair-tiles in flight (P+2*NP < NPAIR always) ----
    if (leader) {
        stagePair(hg, vg, P, buf0a, mb0);
        stagePair(hg, vg, P + NP, buf1a, mb1);
    }

    int buf = 0;
    for (int pi = P; pi < NPAIR; pi += NP, buf ^= 1) {
        if (buf == 0) { waitBar(mb0, ph0); ph0 ^= 1; }
        else          { waitBar(mb1, ph1); ph1 ^= 1; }

        const float* base = buf ? buf1f : buf0f;
        dots(A, base, a, c, t0, lane);             // batch 2pi
        dots(B, base + 128, a, c, t0, lane);       // batch 2pi+1 (+512B)
        reduceTail(A, Nval, a, c, k2, accRp, accR0, accR1);  // interleaves w/ dots(B)

        __syncwarp();                              // all lanes done with buffer
        const int pp = pi + 2 * NP;
        if (leader && pp < NPAIR)
            stagePair(hg, vg, pp, buf ? buf1a : buf0a, buf ? mb1 : mb0);

        reduceTail(B, Nval, a, c, k2, accRp, accR0, accR1);
    }

    // ---- block-level reduction ----
    if (c == a && k2 == 0) {
        atomicAdd(&sAcc[0],         (double)accRp);
        atomicAdd(&sAcc[1 + 2 * a], (double)accR0);
        atomicAdd(&sAcc[2 + 2 * a], (double)accR1);
    }
    __syncthreads();

    if (tid < 9) atomicAdd(&gAcc[tid], sAcc[tid]);
    __threadfence();
    __syncthreads();

    if (tid == 0) {
        const unsigned old = atomicInc(&gCount, GRID - 1);
        sLast = (old == GRID - 1) ? 1 : 0;
    }
    __syncthreads();

    if (sLast && tid == 0) {
        __threadfence();
        const double inv = 1.0 / (double)BATCH;
        double r[9];
        #pragma unroll
        for (int i = 0; i < 9; i++) {
            r[i] = __ldcg(&gAcc[i]);
            __stcg(&gAcc[i], 0.0);
        }
        double s = 0.0;
        #pragma unroll
        for (int i = 1; i < 9; i++) s += r[i] * inv;
        if (out_size >= 1) out[0] = (float)(r[0] * inv);
        if (out_size >= 10) {
            #pragma unroll
            for (int i = 0; i < 8; i++) out[1 + i] = (float)(r[1 + i] * inv);
            out[9] = (float)s;
        }
    }
}

extern "C" void kernel_launch(void* const* d_in, const int* in_sizes, int n_in,
                              void* d_out, int out_size)
{
    const float* h = (const float*)d_in[0];
    const float* v = (const float*)d_in[1];
    const float* N = (const float*)d_in[2];
    float* out = (float*)d_out;

    cudaFuncSetAttribute(se_fused_kernel,
                         cudaFuncAttributeMaxDynamicSharedMemorySize, SMEM_BYTES);
    se_fused_kernel<<<GRID, THREADS, SMEM_BYTES>>>(h, v, N, out, out_size);
}